// round 3
// baseline (speedup 1.0000x reference)
#include <cuda_runtime.h>

#define BATCH 2
#define T 2048
#define D 1024
#define H 16
#define HD 64

// Scratch (allocation-free): head-split projections + attention output
__device__ float g_Q[BATCH*H*T*HD];
__device__ float g_K[BATCH*H*T*HD];
__device__ float g_V[BATCH*H*T*HD];
__device__ float g_O[BATCH*T*D];

// ---------------------------------------------------------------------------
// Projection GEMM: C[row][col] = dot(X[row], W[col])  (C = X @ W^T)
// 64x64 block tile, BK=16, 4x4 per thread, scatter to [b,h,t,n]
// ---------------------------------------------------------------------------
__global__ __launch_bounds__(256) void proj_gemm(
    const float* __restrict__ qin, const float* __restrict__ kin,
    const float* __restrict__ vin,
    const float* __restrict__ Wq, const float* __restrict__ Wk,
    const float* __restrict__ Wv)
{
    __shared__ float As[16][64];
    __shared__ float Bs[16][64];

    const float* X; const float* W; float* out;
    if (blockIdx.z == 0)      { X = qin; W = Wq; out = g_Q; }
    else if (blockIdx.z == 1) { X = kin; W = Wk; out = g_K; }
    else                      { X = vin; W = Wv; out = g_V; }

    int row0 = blockIdx.y * 64, col0 = blockIdx.x * 64;
    int tid = threadIdx.x;
    int tx = tid & 15, ty = tid >> 4;
    int lm = tid >> 2, lk = (tid & 3) * 4;

    float acc[4][4] = {};

    for (int k0 = 0; k0 < D; k0 += 16) {
        float4 av = *(const float4*)(X + (size_t)(row0 + lm) * D + k0 + lk);
        float4 bv = *(const float4*)(W + (size_t)(col0 + lm) * D + k0 + lk);
        __syncthreads();
        As[lk+0][lm] = av.x; As[lk+1][lm] = av.y;
        As[lk+2][lm] = av.z; As[lk+3][lm] = av.w;
        Bs[lk+0][lm] = bv.x; Bs[lk+1][lm] = bv.y;
        Bs[lk+2][lm] = bv.z; Bs[lk+3][lm] = bv.w;
        __syncthreads();
        #pragma unroll
        for (int kk = 0; kk < 16; kk++) {
            float4 a4 = *(const float4*)&As[kk][ty*4];
            float4 b4 = *(const float4*)&Bs[kk][tx*4];
            float ar[4] = {a4.x, a4.y, a4.z, a4.w};
            float br[4] = {b4.x, b4.y, b4.z, b4.w};
            #pragma unroll
            for (int i = 0; i < 4; i++)
                #pragma unroll
                for (int j = 0; j < 4; j++)
                    acc[i][j] = fmaf(ar[i], br[j], acc[i][j]);
        }
    }

    // Scatter into [b, h, t, n] head-split layout
    #pragma unroll
    for (int i = 0; i < 4; i++) {
        int row = row0 + ty*4 + i;
        int bb = row >> 11, t = row & 2047;
        #pragma unroll
        for (int j = 0; j < 4; j++) {
            int col = col0 + tx*4 + j;
            int h = col >> 6, d = col & 63;
            out[(((size_t)bb*H + h)*T + t)*HD + d] = acc[i][j];
        }
    }
}

// ---------------------------------------------------------------------------
// Flash attention: per (b,h), BR=64 q rows per CTA, BC=64 keys per iter.
// 8 warps x 8 q-rows; lane owns cols {lane, lane+32}.
// ---------------------------------------------------------------------------
__global__ __launch_bounds__(256) void attn_kernel()
{
    extern __shared__ float smem[];
    float* Qs = smem;          // [64][64]  Qs[r][k]
    float* Ks = smem + 4096;   // [64][64]  dim-major: Ks[k][j]
    float* Vs = smem + 8192;   // [64][64]  Vs[j][d]
    float* Ps = smem + 12288;  // [64][64]  Ps[r][j]

    int bh = blockIdx.y;
    int qt0 = blockIdx.x * 64;
    const float* Qg = g_Q + (size_t)bh * T * HD + (size_t)qt0 * HD;
    const float* Kg = g_K + (size_t)bh * T * HD;
    const float* Vg = g_V + (size_t)bh * T * HD;

    int tid = threadIdx.x;
    int lane = tid & 31;
    int warp = tid >> 5;
    int r0 = warp * 8;

    // Load Q tile
    for (int i = tid; i < 64 * 16; i += 256) {
        int r = i >> 4, c4 = (i & 15) * 4;
        *(float4*)(Qs + r*64 + c4) = *(const float4*)(Qg + r*64 + c4);
    }

    float m_i[8], l_i[8], o0[8], o1[8];
    #pragma unroll
    for (int r = 0; r < 8; r++) { m_i[r] = -1e30f; l_i[r] = 0.f; o0[r] = 0.f; o1[r] = 0.f; }

    for (int kc = 0; kc < T; kc += 64) {
        __syncthreads();
        // Load K (transposed to dim-major) and V
        for (int i = tid; i < 64 * 16; i += 256) {
            int r = i >> 4, c4 = (i & 15) * 4;
            float4 kv = *(const float4*)(Kg + (size_t)(kc + r)*64 + c4);
            Ks[(c4+0)*64 + r] = kv.x;
            Ks[(c4+1)*64 + r] = kv.y;
            Ks[(c4+2)*64 + r] = kv.z;
            Ks[(c4+3)*64 + r] = kv.w;
            *(float4*)(Vs + r*64 + c4) = *(const float4*)(Vg + (size_t)(kc + r)*64 + c4);
        }
        __syncthreads();

        // S = Q K^T for this tile: lane computes cols {lane, lane+32} x 8 rows
        float s0[8], s1[8];
        #pragma unroll
        for (int r = 0; r < 8; r++) { s0[r] = 0.f; s1[r] = 0.f; }
        #pragma unroll 4
        for (int k = 0; k < 64; k++) {
            float kv1 = Ks[k*64 + lane];
            float kv2 = Ks[k*64 + lane + 32];
            #pragma unroll
            for (int r = 0; r < 8; r++) {
                float qv = Qs[(r0 + r)*64 + k];   // broadcast
                s0[r] = fmaf(qv, kv1, s0[r]);
                s1[r] = fmaf(qv, kv2, s1[r]);
            }
        }

        // Online softmax (scale 1/sqrt(64) = 0.125)
        #pragma unroll
        for (int r = 0; r < 8; r++) {
            float sa = s0[r] * 0.125f;
            float sb = s1[r] * 0.125f;
            float mx = fmaxf(sa, sb);
            #pragma unroll
            for (int off = 16; off; off >>= 1)
                mx = fmaxf(mx, __shfl_xor_sync(0xffffffffu, mx, off));
            float mnew = fmaxf(m_i[r], mx);
            float p0 = __expf(sa - mnew);
            float p1 = __expf(sb - mnew);
            float alpha = __expf(m_i[r] - mnew);
            float rs = p0 + p1;
            #pragma unroll
            for (int off = 16; off; off >>= 1)
                rs += __shfl_xor_sync(0xffffffffu, rs, off);
            l_i[r] = l_i[r] * alpha + rs;
            m_i[r] = mnew;
            o0[r] *= alpha;
            o1[r] *= alpha;
            Ps[(r0 + r)*64 + lane] = p0;
            Ps[(r0 + r)*64 + lane + 32] = p1;
        }
        __syncwarp();

        // O += P V : lane owns dims {lane, lane+32}
        #pragma unroll 4
        for (int j = 0; j < 64; j++) {
            float v1 = Vs[j*64 + lane];
            float v2 = Vs[j*64 + lane + 32];
            #pragma unroll
            for (int r = 0; r < 8; r++) {
                float p = Ps[(r0 + r)*64 + j];   // broadcast
                o0[r] = fmaf(p, v1, o0[r]);
                o1[r] = fmaf(p, v2, o1[r]);
            }
        }
    }

    // Normalize and write O as [b, t, h*64+d]
    int b = bh >> 4, h = bh & 15;
    #pragma unroll
    for (int r = 0; r < 8; r++) {
        float inv = 1.0f / l_i[r];
        int t = qt0 + r0 + r;
        float* op = g_O + ((size_t)b*T + t)*D + h*HD;
        op[lane]      = o0[r] * inv;
        op[lane + 32] = o1[r] * inv;
    }
}

// ---------------------------------------------------------------------------
// Output projection: out = O @ Wo^T + bo
// ---------------------------------------------------------------------------
__global__ __launch_bounds__(256) void out_gemm(
    const float* __restrict__ Wo, const float* __restrict__ bo,
    float* __restrict__ out)
{
    __shared__ float As[16][64];
    __shared__ float Bs[16][64];

    int row0 = blockIdx.y * 64, col0 = blockIdx.x * 64;
    int tid = threadIdx.x;
    int tx = tid & 15, ty = tid >> 4;
    int lm = tid >> 2, lk = (tid & 3) * 4;

    float acc[4][4] = {};

    for (int k0 = 0; k0 < D; k0 += 16) {
        float4 av = *(const float4*)(g_O + (size_t)(row0 + lm) * D + k0 + lk);
        float4 bv = *(const float4*)(Wo + (size_t)(col0 + lm) * D + k0 + lk);
        __syncthreads();
        As[lk+0][lm] = av.x; As[lk+1][lm] = av.y;
        As[lk+2][lm] = av.z; As[lk+3][lm] = av.w;
        Bs[lk+0][lm] = bv.x; Bs[lk+1][lm] = bv.y;
        Bs[lk+2][lm] = bv.z; Bs[lk+3][lm] = bv.w;
        __syncthreads();
        #pragma unroll
        for (int kk = 0; kk < 16; kk++) {
            float4 a4 = *(const float4*)&As[kk][ty*4];
            float4 b4 = *(const float4*)&Bs[kk][tx*4];
            float ar[4] = {a4.x, a4.y, a4.z, a4.w};
            float br[4] = {b4.x, b4.y, b4.z, b4.w};
            #pragma unroll
            for (int i = 0; i < 4; i++)
                #pragma unroll
                for (int j = 0; j < 4; j++)
                    acc[i][j] = fmaf(ar[i], br[j], acc[i][j]);
        }
    }

    #pragma unroll
    for (int i = 0; i < 4; i++) {
        int row = row0 + ty*4 + i;
        #pragma unroll
        for (int j = 0; j < 4; j++) {
            int col = col0 + tx*4 + j;
            out[(size_t)row * D + col] = acc[i][j] + bo[col];
        }
    }
}

// ---------------------------------------------------------------------------
extern "C" void kernel_launch(void* const* d_in, const int* in_sizes, int n_in,
                              void* d_out, int out_size)
{
    const float* k  = (const float*)d_in[0];
    const float* q  = (const float*)d_in[1];
    const float* v  = (const float*)d_in[2];
    const float* Wk = (const float*)d_in[3];
    const float* Wq = (const float*)d_in[4];
    const float* Wv = (const float*)d_in[5];
    const float* Wo = (const float*)d_in[6];
    const float* bo = (const float*)d_in[7];
    float* out = (float*)d_out;

    cudaFuncSetAttribute(attn_kernel,
                         cudaFuncAttributeMaxDynamicSharedMemorySize, 65536);

    // 1) Q/K/V projections into head-split layout (z-fused)
    proj_gemm<<<dim3(D/64, (BATCH*T)/64, 3), 256>>>(q, k, v, Wq, Wk, Wv);

    // 2) Flash attention per (b,h)
    attn_kernel<<<dim3(T/64, BATCH*H), 256, 65536>>>();

    // 3) Output projection + bias
    out_gemm<<<dim3(D/64, (BATCH*T)/64), 256>>>(Wo, bo, out);
}